// round 15
// baseline (speedup 1.0000x reference)
#include <cuda_runtime.h>
#include <math.h>
#include <stdint.h>

#define BSG   8          // B*S graphs
#define L     1024       // nodes per graph
#define C     128        // feature dim
#define HIMG  256
#define WIMG  256
#define NEG   0.2f
#define LNEPS 1e-5f
#define NS    4          // j-splits
#define JSPAN (L / NS)   // 256

// ---------------- scratch (static device globals; no allocs) ----------------
__device__ uint32_t g_adj[BSG][L][L / 32];        // 1 MB adjacency bitmask
__device__ float    g_wf[BSG * L * C];            // Wf for current layer
__device__ float    g_h1[BSG * L * C];            // layer-1 output
__device__ float    g_esrc[BSG * L * 4];
__device__ float    g_edst[BSG * L * 4];
__device__ float    g_pacc[NS * BSG * L * C];     // 16 MB partial accumulators
__device__ float    g_pl[NS * BSG * L * 4];       // partial softmax sums [row][head]
__device__ uint32_t g_tmaxb[BSG * 4];             // encoded per-(graph,head) max e_dst

// ---------------- order-preserving float<->uint for atomicMax ----------------
__device__ __forceinline__ uint32_t fenc(float f) {
    uint32_t u = __float_as_uint(f);
    return (u & 0x80000000u) ? ~u : (u | 0x80000000u);
}
__device__ __forceinline__ float fdec(uint32_t k) {
    uint32_t u = (k & 0x80000000u) ? (k ^ 0x80000000u) : ~k;
    return __uint_as_float(u);
}

// ---------------- packed f32x2 helpers (FFMA2) ----------------
__device__ __forceinline__ unsigned long long dup2(float a) {
    unsigned long long r;
    asm("mov.b64 %0, {%1, %1};" : "=l"(r) : "f"(a));
    return r;
}
__device__ __forceinline__ void ffma2(unsigned long long& d,
                                      unsigned long long a, unsigned long long b) {
    asm("fma.rn.f32x2 %0, %1, %2, %0;" : "+l"(d) : "l"(a), "l"(b));
}
__device__ __forceinline__ float2 unpk(unsigned long long v) {
    float lo, hi;
    asm("mov.b64 {%0, %1}, %2;" : "=f"(lo), "=f"(hi) : "l"(v));
    return make_float2(lo, hi);
}

// ---------------- cp.async helpers ----------------
__device__ __forceinline__ uint32_t smem_u32(const void* p) {
    uint32_t a;
    asm("{ .reg .u64 t; cvta.to.shared.u64 t, %1; cvt.u32.u64 %0, t; }" : "=r"(a) : "l"(p));
    return a;
}
__device__ __forceinline__ void cpa16(uint32_t dst, const void* src) {
    asm volatile("cp.async.ca.shared.global [%0], [%1], 16;" :: "r"(dst), "l"(src) : "memory");
}
#define CPA_COMMIT() asm volatile("cp.async.commit_group;" ::: "memory")
#define CPA_WAIT0()  asm volatile("cp.async.wait_group 0;" ::: "memory")

// ---------------- adjacency ----------------
__global__ void k_adj_init() {
    int idx = blockIdx.x * blockDim.x + threadIdx.x;
    if (blockIdx.x == 0 && threadIdx.x < BSG * 4) g_tmaxb[threadIdx.x] = 0u;
    if (idx >= BSG * L * 32) return;
    int w = idx & 31;
    int i = (idx >> 5) & (L - 1);
    ((uint32_t*)g_adj)[idx] = (w == (i >> 5)) ? (1u << (i & 31)) : 0u;
}

__global__ void k_adj_build(const int* __restrict__ img) {
    int idx = blockIdx.x * blockDim.x + threadIdx.x;
    if (idx >= BSG * HIMG * WIMG) return;
    int x  = idx & (WIMG - 1);
    int y  = (idx >> 8) & (HIMG - 1);
    int gg = idx >> 16;
    const int* base = img + gg * HIMG * WIMG;
    int p = base[y * WIMG + x];

    auto edge = [&](int a, int b) {
        if (a > 0 && b > 0 && a != b) {
            int ai = a - 1, bi = b - 1;
            atomicOr(&g_adj[gg][ai][bi >> 5], 1u << (bi & 31));
            atomicOr(&g_adj[gg][bi][ai >> 5], 1u << (ai & 31));
        }
    };
    if (x + 1 < WIMG) edge(p, base[y * WIMG + x + 1]);
    if (y + 1 < HIMG) {
        edge(p, base[(y + 1) * WIMG + x]);
        if (x + 1 < WIMG) edge(p, base[(y + 1) * WIMG + x + 1]);
        if (x > 0)        edge(p, base[(y + 1) * WIMG + x - 1]);
    }
}

// ---------------- NT GEMM (16-row tiles) + fused e_src/e_dst + tmax ----------------
template<int HEADS>
__global__ void __launch_bounds__(256) k_gemm_nt(const float* __restrict__ in,
                                                 const float* __restrict__ W,
                                                 const float* __restrict__ asrc,
                                                 const float* __restrict__ adst) {
    __shared__ float4 xs[16][9];
    __shared__ float4 ws[128][9];
    int tid = threadIdx.x;
    int gg  = blockIdx.x >> 6;
    int r0  = (blockIdx.x & 63) * 16;
    const float* src = in ? (in + gg * L * C) : (g_h1 + gg * L * C);
    const float4* in4 = (const float4*)src;
    const float4* W4  = (const float4*)W;
    int tx = tid & 31, ty = tid >> 5;
    float acc[2][4] = {};

    for (int k0 = 0; k0 < 32; k0 += 8) {
        if (tid < 128) {
            int r = tid >> 3, kq = tid & 7;
            xs[r][kq] = in4[(r0 + r) * 32 + k0 + kq];
        }
        #pragma unroll
        for (int it = 0; it < 4; it++) {
            int idx = tid + it * 256;
            int o = idx >> 3, kq = idx & 7;
            ws[o][kq] = W4[o * 32 + k0 + kq];
        }
        __syncthreads();
        #pragma unroll
        for (int kq = 0; kq < 8; kq++) {
            float4 xv[2], wv[4];
            #pragma unroll
            for (int rr = 0; rr < 2; rr++) xv[rr] = xs[ty * 2 + rr][kq];
            #pragma unroll
            for (int cc = 0; cc < 4; cc++) wv[cc] = ws[tx + 32 * cc][kq];
            #pragma unroll
            for (int rr = 0; rr < 2; rr++)
                #pragma unroll
                for (int cc = 0; cc < 4; cc++)
                    acc[rr][cc] += xv[rr].x * wv[cc].x + xv[rr].y * wv[cc].y
                                 + xv[rr].z * wv[cc].z + xv[rr].w * wv[cc].w;
        }
        __syncthreads();
    }
    float* ob = g_wf + gg * L * C;
    #pragma unroll
    for (int rr = 0; rr < 2; rr++)
        #pragma unroll
        for (int cc = 0; cc < 4; cc++)
            ob[(r0 + ty * 2 + rr) * C + tx + 32 * cc] = acc[rr][cc];

    float as[4], ad[4];
    #pragma unroll
    for (int cc = 0; cc < 4; cc++) {
        int col = tx + 32 * cc;
        as[cc] = asrc[col];
        ad[cc] = adst[col];
    }
    #pragma unroll
    for (int rr = 0; rr < 2; rr++) {
        int row = r0 + ty * 2 + rr;
        if (HEADS == 4) {
            #pragma unroll
            for (int cc = 0; cc < 4; cc++) {
                float ps = acc[rr][cc] * as[cc];
                float pd = acc[rr][cc] * ad[cc];
                #pragma unroll
                for (int off = 16; off > 0; off >>= 1) {
                    ps += __shfl_xor_sync(0xffffffffu, ps, off);
                    pd += __shfl_xor_sync(0xffffffffu, pd, off);
                }
                if (tx == 0) {
                    g_esrc[(gg * L + row) * 4 + cc] = ps;
                    g_edst[(gg * L + row) * 4 + cc] = pd;
                    atomicMax(&g_tmaxb[gg * 4 + cc], fenc(pd));
                }
            }
        } else {
            float ps = 0.f, pd = 0.f;
            #pragma unroll
            for (int cc = 0; cc < 4; cc++) {
                ps += acc[rr][cc] * as[cc];
                pd += acc[rr][cc] * ad[cc];
            }
            #pragma unroll
            for (int off = 16; off > 0; off >>= 1) {
                ps += __shfl_xor_sync(0xffffffffu, ps, off);
                pd += __shfl_xor_sync(0xffffffffu, pd, off);
            }
            if (tx == 0) {
                g_esrc[(gg * L + row)] = ps;
                g_edst[(gg * L + row)] = pd;
                atomicMax(&g_tmaxb[gg], fenc(pd));
            }
        }
    }
}

// ---------------- partial masked attention over one j-split ----------------
// alpha = mask * max(E1_i*F1_j, E2_i*F2_j)  (factorized, verified).
// 256 threads / 8 warps; warp ig owns 4 f4-cols; lane = (rgrp = lane>>2,
// colq = lane&3); 4 rows x 1 f4 per thread (8 ull acc = 16 regs).
// Row-paired f32x2, double-buffered wf/alpha, ONE barrier per chunk, cp.async.
template<int HEADS>
__global__ void __launch_bounds__(256) k_attn_part() {
    constexpr int TI = 32, JC = 16, HT = HEADS * TI, NCH = JSPAN / JC;
    __shared__ __align__(16) float2 f12_sh[JSPAN * HEADS]; // (F1,F2) per (j,h)
    __shared__ __align__(16) float4 wf_sh[2][JC][32];
    __shared__ __align__(16) float alpha_sh[2][JC * HT];   // [buf][jj][head][row]
    __shared__ uint32_t adj_tr[JSPAN / 32][TI];            // [word][row]
    __shared__ float2 e12_sh[HT];                          // (E1,E2), [head][row]
    __shared__ float l_sh[HT];                             // [head][row]

    int tid  = threadIdx.x;
    int lane = tid & 31, ig = tid >> 5;          // warp 0..7
    int b    = blockIdx.x;                       // BSG*32*NS blocks
    int js   = b & (NS - 1);
    int it   = (b >> 2) & 31;
    int gg   = b >> 7;
    int i0   = it * TI;
    int j0   = js * JSPAN;

    // F1/F2 table: F1 = exp(t - tmax), F2 = exp(NEG*(t - tmax))
    {
        const float* tg = g_edst + (gg * L + j0) * HEADS;
        for (int idx = tid; idx < JSPAN * HEADS; idx += 256) {
            int h = idx & (HEADS - 1);
            float tmax = fdec(g_tmaxb[gg * HEADS + h]);
            float d = tg[idx] - tmax;
            f12_sh[idx] = make_float2(__expf(d), __expf(NEG * d));
        }
    }
    for (int idx = tid; idx < (JSPAN / 32) * TI; idx += 256) {
        int w = idx / TI, r = idx % TI;
        adj_tr[w][r] = g_adj[gg][i0 + r][(j0 >> 5) + w];
    }
    // E1/E2 per (row,head): m = leaky(s+tmax)
    if (tid < HT) {
        int r = tid / HEADS, h = tid & (HEADS - 1);
        float s = g_esrc[(gg * L + i0 + r) * HEADS + h];
        float sm0 = s + fdec(g_tmaxb[gg * HEADS + h]);
        float m = fmaxf(sm0, NEG * sm0);
        e12_sh[h * TI + r] = make_float2(__expf(sm0 - m), __expf(NEG * sm0 - m));
        l_sh[h * TI + r] = 0.f;
    }
    __syncthreads();

    constexpr int NSUB = 256 / HT;               // 2 (H4), 8 (H1)
    const int pair = tid & (HT - 1);             // pair = ph*TI + pr
    const int sub  = tid / HT;
    const int ph   = pair / TI, pr = pair & (TI - 1);
    const float2 E = e12_sh[pair];
    float lacc = 0.f;

    // consumer mapping: warp ig owns f4-cols [ig*4, ig*4+4)
    const int colq  = lane & 3;                  // f4 col within warp group
    const int rgrp  = lane >> 2;                 // 4-row group 0..7
    const int dcol4 = ig * 4 + colq;             // f4 col 0..31
    const int myh   = (HEADS == 4) ? (ig >> 1) : 0;  // head (constant per warp)
    unsigned long long acc[8];                   // 2 row-pairs x 4 cols
    #pragma unroll
    for (int k = 0; k < 8; k++) acc[k] = 0ULL;
    const float4* wfg = (const float4*)(g_wf + (gg * L + j0) * C);
    const uint32_t wfb = smem_u32(&wf_sh[0][0][0]);

    // producer: cp.async Wf tile + alpha STS into buffer nb
    auto fill = [&](int jb, int nb) {
        #pragma unroll
        for (int it2 = 0; it2 < 2; it2++) {
            int idx = tid + it2 * 256;
            uint32_t dst = wfb + (uint32_t)(((nb * JC + (idx >> 5)) * 32 + (idx & 31)) * 16);
            cpa16(dst, &wfg[(jb + (idx >> 5)) * 32 + (idx & 31)]);
        }
        CPA_COMMIT();
        uint32_t wd = adj_tr[jb >> 5][pr];
        int bshift = jb & 16;
        #pragma unroll
        for (int jj = sub; jj < JC; jj += NSUB) {
            float2 f = f12_sh[(jb + jj) * HEADS + ph];
            float a = fmaxf(E.x * f.x, E.y * f.y);
            a = ((wd >> (bshift + jj)) & 1u) ? a : 0.f;
            lacc += a;
            alpha_sh[nb][jj * HT + pair] = a;
        }
    };

    fill(0, 0);
    CPA_WAIT0();
    __syncthreads();

    for (int ch = 0; ch < NCH; ch++) {           // 16 chunks
        int cur = ch & 1;
        if (ch + 1 < NCH) fill((ch + 1) * JC, cur ^ 1);
        // acc += alpha * Wf : row-paired f32x2, alpha pairs native, w duplicated
        #pragma unroll
        for (int jj = 0; jj < JC; jj++) {
            float4 w4 = wf_sh[cur][jj][dcol4];
            unsigned long long wd0 = dup2(w4.x), wd1 = dup2(w4.y);
            unsigned long long wd2 = dup2(w4.z), wd3 = dup2(w4.w);
            const ulonglong2* ap =
                (const ulonglong2*)&alpha_sh[cur][jj * HT + myh * TI + rgrp * 4];
            ulonglong2 q0 = ap[0];               // 2 row-pairs (4 rows)
            ffma2(acc[0], q0.x, wd0); ffma2(acc[1], q0.x, wd1);
            ffma2(acc[2], q0.x, wd2); ffma2(acc[3], q0.x, wd3);
            ffma2(acc[4], q0.y, wd0); ffma2(acc[5], q0.y, wd1);
            ffma2(acc[6], q0.y, wd2); ffma2(acc[7], q0.y, wd3);
        }
        CPA_WAIT0();
        __syncthreads();
    }

    if (NSUB == 1) l_sh[pair] = lacc;
    else atomicAdd(&l_sh[pair], lacc);
    __syncthreads();

    // write partials — l_sh is [head][row]; g_pl is [row][head]: transpose.
    if (tid < HT) {
        int r = tid / HEADS, h = tid % HEADS;
        g_pl[((js * BSG + gg) * L + i0 + r) * HEADS + h] = l_sh[h * TI + r];
    }
    float4* po = (float4*)(g_pacc + ((js * BSG + gg) * L) * C);
    #pragma unroll
    for (int p = 0; p < 2; p++) {
        float2 u0 = unpk(acc[p * 4 + 0]);
        float2 u1 = unpk(acc[p * 4 + 1]);
        float2 u2 = unpk(acc[p * 4 + 2]);
        float2 u3 = unpk(acc[p * 4 + 3]);
        int r0loc = rgrp * 4 + 2 * p;
        po[(i0 + r0loc) * 32 + dcol4]     = make_float4(u0.x, u1.x, u2.x, u3.x);
        po[(i0 + r0loc + 1) * 32 + dcol4] = make_float4(u0.y, u1.y, u2.y, u3.y);
    }
}

// ---------------- combine partials + epilogue ----------------
template<int HEADS, int MODE>
__global__ void __launch_bounds__(256) k_combine(const float* __restrict__ feats,
                                                 const float* __restrict__ gamma,
                                                 const float* __restrict__ beta,
                                                 float* __restrict__ out) {
    int gid  = blockIdx.x * 256 + threadIdx.x;   // BSG*L*32 threads
    int dcol = gid & 31;
    int row  = gid >> 5;
    constexpr int DH = 32 / HEADS;
    int h = dcol / DH;

    float l = 0.f;
    float4 v = make_float4(0.f, 0.f, 0.f, 0.f);
    #pragma unroll
    for (int ns = 0; ns < NS; ns++) {
        l += g_pl[(ns * BSG * L + row) * HEADS + h];
        float4 p = ((const float4*)(g_pacc + ns * BSG * L * C))[row * 32 + dcol];
        v.x += p.x; v.y += p.y; v.z += p.z; v.w += p.w;
    }
    float rl = 1.f / l;
    v.x *= rl; v.y *= rl; v.z *= rl; v.w *= rl;

    if (MODE == 0) {
        v.x = v.x > 0.f ? v.x : expm1f(v.x);
        v.y = v.y > 0.f ? v.y : expm1f(v.y);
        v.z = v.z > 0.f ? v.z : expm1f(v.z);
        v.w = v.w > 0.f ? v.w : expm1f(v.w);
        ((float4*)g_h1)[row * 32 + dcol] = v;
    } else {
        float4 y = ((const float4*)feats)[row * 32 + dcol];
        y.x += v.x; y.y += v.y; y.z += v.z; y.w += v.w;
        float sm = y.x + y.y + y.z + y.w;
        float sq = y.x * y.x + y.y * y.y + y.z * y.z + y.w * y.w;
        #pragma unroll
        for (int off = 16; off > 0; off >>= 1) {
            sm += __shfl_xor_sync(0xffffffffu, sm, off);
            sq += __shfl_xor_sync(0xffffffffu, sq, off);
        }
        float mean = sm * (1.f / 128.f);
        float var  = sq * (1.f / 128.f) - mean * mean;
        float inv  = rsqrtf(var + LNEPS);
        float4 gm = ((const float4*)gamma)[dcol];
        float4 bt = ((const float4*)beta)[dcol];
        float4 o;
        o.x = (y.x - mean) * inv * gm.x + bt.x;
        o.y = (y.y - mean) * inv * gm.y + bt.y;
        o.z = (y.z - mean) * inv * gm.z + bt.z;
        o.w = (y.w - mean) * inv * gm.w + bt.w;
        ((float4*)out)[row * 32 + dcol] = o;
    }
}

// ---------------- launch ----------------
extern "C" void kernel_launch(void* const* d_in, const int* in_sizes, int n_in,
                              void* d_out, int out_size) {
    const float* seg_feats = (const float*)d_in[0];
    const int*   seg_img   = (const int*)d_in[1];
    const float* W1    = (const float*)d_in[3];
    const float* asrc1 = (const float*)d_in[4];
    const float* adst1 = (const float*)d_in[5];
    const float* W2    = (const float*)d_in[6];
    const float* asrc2 = (const float*)d_in[7];
    const float* adst2 = (const float*)d_in[8];
    const float* gamma = (const float*)d_in[9];
    const float* beta  = (const float*)d_in[10];
    float* out = (float*)d_out;

    k_adj_init <<<(BSG * L * 32 + 255) / 256, 256>>>();
    k_adj_build<<<(BSG * HIMG * WIMG + 255) / 256, 256>>>(seg_img);

    // layer 1 (gemm epilogue also feeds g_tmaxb via atomicMax)
    k_gemm_nt<4><<<BSG * 64, 256>>>(seg_feats, W1, asrc1, adst1);
    k_attn_part<4><<<BSG * 32 * NS, 256>>>();
    k_combine<4, 0><<<BSG * L * 32 / 256, 256>>>(nullptr, nullptr, nullptr, nullptr);

    // layer 2 — g_tmaxb zeroed by k_adj_init each launch; layer-2 atomics land on
    // layer-1 maxima, still a valid (deterministic) upper bound for the shift.
    k_gemm_nt<1><<<BSG * 64, 256>>>(nullptr, W2, asrc2, adst2);
    k_attn_part<1><<<BSG * 32 * NS, 256>>>();
    k_combine<1, 1><<<BSG * L * 32 / 256, 256>>>(seg_feats, gamma, beta, out);
}

// round 16
// speedup vs baseline: 1.0323x; 1.0323x over previous
#include <cuda_runtime.h>
#include <math.h>
#include <stdint.h>

#define BSG   8          // B*S graphs
#define L     1024       // nodes per graph
#define C     128        // feature dim
#define HIMG  256
#define WIMG  256
#define NEG   0.2f
#define LNEPS 1e-5f
#define NS    4          // j-splits
#define JSPAN (L / NS)   // 256

// ---------------- scratch (static device globals; no allocs) ----------------
__device__ uint32_t g_adj[BSG][L][L / 32];        // 1 MB adjacency bitmask
__device__ float    g_wf[BSG * L * C];            // Wf for current layer
__device__ float    g_pacc[NS * BSG * L * C];     // 16 MB partial accumulators
__device__ float    g_pl[NS * BSG * L * 4];       // partial softmax sums [row][head]
__device__ float    g_esrc[BSG * L * 4];
__device__ float    g_edst[BSG * L * 4];
__device__ uint32_t g_tmaxb[BSG * 4];             // encoded per-(graph,head) max e_dst

// ---------------- order-preserving float<->uint for atomicMax ----------------
__device__ __forceinline__ uint32_t fenc(float f) {
    uint32_t u = __float_as_uint(f);
    return (u & 0x80000000u) ? ~u : (u | 0x80000000u);
}
__device__ __forceinline__ float fdec(uint32_t k) {
    uint32_t u = (k & 0x80000000u) ? (k ^ 0x80000000u) : ~k;
    return __uint_as_float(u);
}

// ---------------- packed f32x2 helpers (FFMA2) ----------------
__device__ __forceinline__ unsigned long long dup2(float a) {
    unsigned long long r;
    asm("mov.b64 %0, {%1, %1};" : "=l"(r) : "f"(a));
    return r;
}
__device__ __forceinline__ void ffma2(unsigned long long& d,
                                      unsigned long long a, unsigned long long b) {
    asm("fma.rn.f32x2 %0, %1, %2, %0;" : "+l"(d) : "l"(a), "l"(b));
}
__device__ __forceinline__ float2 unpk(unsigned long long v) {
    float lo, hi;
    asm("mov.b64 {%0, %1}, %2;" : "=f"(lo), "=f"(hi) : "l"(v));
    return make_float2(lo, hi);
}

// ---------------- cp.async helpers ----------------
__device__ __forceinline__ uint32_t smem_u32(const void* p) {
    uint32_t a;
    asm("{ .reg .u64 t; cvta.to.shared.u64 t, %1; cvt.u32.u64 %0, t; }" : "=r"(a) : "l"(p));
    return a;
}
__device__ __forceinline__ void cpa16(uint32_t dst, const void* src) {
    asm volatile("cp.async.ca.shared.global [%0], [%1], 16;" :: "r"(dst), "l"(src) : "memory");
}
#define CPA_COMMIT() asm volatile("cp.async.commit_group;" ::: "memory")
#define CPA_WAIT0()  asm volatile("cp.async.wait_group 0;" ::: "memory")

// ---------------- adjacency ----------------
__global__ void k_adj_init() {
    int idx = blockIdx.x * blockDim.x + threadIdx.x;
    if (blockIdx.x == 0 && threadIdx.x < BSG * 4) g_tmaxb[threadIdx.x] = 0u;
    if (idx >= BSG * L * 32) return;
    int w = idx & 31;
    int i = (idx >> 5) & (L - 1);
    ((uint32_t*)g_adj)[idx] = (w == (i >> 5)) ? (1u << (i & 31)) : 0u;
}

__global__ void k_adj_build(const int* __restrict__ img) {
    int idx = blockIdx.x * blockDim.x + threadIdx.x;
    if (idx >= BSG * HIMG * WIMG) return;
    int x  = idx & (WIMG - 1);
    int y  = (idx >> 8) & (HIMG - 1);
    int gg = idx >> 16;
    const int* base = img + gg * HIMG * WIMG;
    int p = base[y * WIMG + x];

    auto edge = [&](int a, int b) {
        if (a > 0 && b > 0 && a != b) {
            int ai = a - 1, bi = b - 1;
            atomicOr(&g_adj[gg][ai][bi >> 5], 1u << (bi & 31));
            atomicOr(&g_adj[gg][bi][ai >> 5], 1u << (ai & 31));
        }
    };
    if (x + 1 < WIMG) edge(p, base[y * WIMG + x + 1]);
    if (y + 1 < HIMG) {
        edge(p, base[(y + 1) * WIMG + x]);
        if (x + 1 < WIMG) edge(p, base[(y + 1) * WIMG + x + 1]);
        if (x > 0)        edge(p, base[(y + 1) * WIMG + x - 1]);
    }
}

// ---------------- NT GEMM (16-row tiles) + fused e_src/e_dst + tmax ----------------
// If in == nullptr (layer 2): input = ELU(sum_ns g_pacc / sum_ns g_pl) computed
// inline (fused layer-1 combine; each h1 row is read by exactly one block).
template<int HEADS>
__global__ void __launch_bounds__(256) k_gemm_nt(const float* __restrict__ in,
                                                 const float* __restrict__ W,
                                                 const float* __restrict__ asrc,
                                                 const float* __restrict__ adst) {
    __shared__ float4 xs[16][9];
    __shared__ float4 ws[128][9];
    __shared__ float linv_sh[16][4];
    int tid = threadIdx.x;
    int gg  = blockIdx.x >> 6;
    int r0  = (blockIdx.x & 63) * 16;
    const float4* in4 = in ? (const float4*)(in + gg * L * C) : nullptr;
    const float4* W4  = (const float4*)W;
    int tx = tid & 31, ty = tid >> 5;
    float acc[2][4] = {};

    if (!in && tid < 64) {    // 1/l per (row, layer-1 head)
        int r = tid >> 2, h = tid & 3;
        float l = 0.f;
        #pragma unroll
        for (int ns = 0; ns < NS; ns++)
            l += g_pl[(ns * BSG * L + gg * L + r0 + r) * 4 + h];
        linv_sh[r][h] = 1.f / l;
    }
    if (!in) __syncthreads();

    for (int k0 = 0; k0 < 32; k0 += 8) {
        if (tid < 128) {
            int r = tid >> 3, kq = tid & 7;
            if (in) {
                xs[r][kq] = in4[(r0 + r) * 32 + k0 + kq];
            } else {
                int col4 = k0 + kq;
                int base = (gg * L + r0 + r) * 32 + col4;
                float4 v = ((const float4*)g_pacc)[base];
                #pragma unroll
                for (int ns = 1; ns < NS; ns++) {
                    float4 p = ((const float4*)g_pacc)[ns * BSG * L * 32 + base];
                    v.x += p.x; v.y += p.y; v.z += p.z; v.w += p.w;
                }
                float rl = linv_sh[r][col4 >> 3];
                v.x *= rl; v.y *= rl; v.z *= rl; v.w *= rl;
                v.x = v.x > 0.f ? v.x : expm1f(v.x);
                v.y = v.y > 0.f ? v.y : expm1f(v.y);
                v.z = v.z > 0.f ? v.z : expm1f(v.z);
                v.w = v.w > 0.f ? v.w : expm1f(v.w);
                xs[r][kq] = v;
            }
        }
        #pragma unroll
        for (int it = 0; it < 4; it++) {
            int idx = tid + it * 256;
            int o = idx >> 3, kq = idx & 7;
            ws[o][kq] = W4[o * 32 + k0 + kq];
        }
        __syncthreads();
        #pragma unroll
        for (int kq = 0; kq < 8; kq++) {
            float4 xv[2], wv[4];
            #pragma unroll
            for (int rr = 0; rr < 2; rr++) xv[rr] = xs[ty * 2 + rr][kq];
            #pragma unroll
            for (int cc = 0; cc < 4; cc++) wv[cc] = ws[tx + 32 * cc][kq];
            #pragma unroll
            for (int rr = 0; rr < 2; rr++)
                #pragma unroll
                for (int cc = 0; cc < 4; cc++)
                    acc[rr][cc] += xv[rr].x * wv[cc].x + xv[rr].y * wv[cc].y
                                 + xv[rr].z * wv[cc].z + xv[rr].w * wv[cc].w;
        }
        __syncthreads();
    }
    float* ob = g_wf + gg * L * C;
    #pragma unroll
    for (int rr = 0; rr < 2; rr++)
        #pragma unroll
        for (int cc = 0; cc < 4; cc++)
            ob[(r0 + ty * 2 + rr) * C + tx + 32 * cc] = acc[rr][cc];

    float as[4], ad[4];
    #pragma unroll
    for (int cc = 0; cc < 4; cc++) {
        int col = tx + 32 * cc;
        as[cc] = asrc[col];
        ad[cc] = adst[col];
    }
    #pragma unroll
    for (int rr = 0; rr < 2; rr++) {
        int row = r0 + ty * 2 + rr;
        if (HEADS == 4) {
            #pragma unroll
            for (int cc = 0; cc < 4; cc++) {
                float ps = acc[rr][cc] * as[cc];
                float pd = acc[rr][cc] * ad[cc];
                #pragma unroll
                for (int off = 16; off > 0; off >>= 1) {
                    ps += __shfl_xor_sync(0xffffffffu, ps, off);
                    pd += __shfl_xor_sync(0xffffffffu, pd, off);
                }
                if (tx == 0) {
                    g_esrc[(gg * L + row) * 4 + cc] = ps;
                    g_edst[(gg * L + row) * 4 + cc] = pd;
                    atomicMax(&g_tmaxb[gg * 4 + cc], fenc(pd));
                }
            }
        } else {
            float ps = 0.f, pd = 0.f;
            #pragma unroll
            for (int cc = 0; cc < 4; cc++) {
                ps += acc[rr][cc] * as[cc];
                pd += acc[rr][cc] * ad[cc];
            }
            #pragma unroll
            for (int off = 16; off > 0; off >>= 1) {
                ps += __shfl_xor_sync(0xffffffffu, ps, off);
                pd += __shfl_xor_sync(0xffffffffu, pd, off);
            }
            if (tx == 0) {
                g_esrc[(gg * L + row)] = ps;
                g_edst[(gg * L + row)] = pd;
                atomicMax(&g_tmaxb[gg], fenc(pd));
            }
        }
    }
}

// ---------------- partial masked attention over one j-split ----------------
// Round-14 configuration (best verified): 128 threads / 4 warps, 8 rows/thread,
// column-group tiling, row-paired f32x2 acc, double buffer + cp.async,
// alpha = mask * max(E1_i*F1_j, E2_i*F2_j).
template<int HEADS>
__global__ void __launch_bounds__(128) k_attn_part() {
    constexpr int TI = 32, JC = 16, HT = HEADS * TI, NCH = JSPAN / JC;
    __shared__ __align__(16) float2 f12_sh[JSPAN * HEADS];
    __shared__ __align__(16) float4 wf_sh[2][JC][32];
    __shared__ __align__(16) float alpha_sh[2][JC * HT];
    __shared__ uint32_t adj_tr[JSPAN / 32][TI];
    __shared__ float2 e12_sh[HT];
    __shared__ float l_sh[HT];

    int tid  = threadIdx.x;
    int lane = tid & 31, ig = tid >> 5;
    int b    = blockIdx.x;
    int js   = b & (NS - 1);
    int it   = (b >> 2) & 31;
    int gg   = b >> 7;
    int i0   = it * TI;
    int j0   = js * JSPAN;

    {
        const float* tg = g_edst + (gg * L + j0) * HEADS;
        for (int idx = tid; idx < JSPAN * HEADS; idx += 128) {
            int h = idx & (HEADS - 1);
            float tmax = fdec(g_tmaxb[gg * HEADS + h]);
            float d = tg[idx] - tmax;
            f12_sh[idx] = make_float2(__expf(d), __expf(NEG * d));
        }
    }
    for (int idx = tid; idx < (JSPAN / 32) * TI; idx += 128) {
        int w = idx / TI, r = idx % TI;
        adj_tr[w][r] = g_adj[gg][i0 + r][(j0 >> 5) + w];
    }
    if (tid < HT) {
        int r = tid / HEADS, h = tid & (HEADS - 1);
        float s = g_esrc[(gg * L + i0 + r) * HEADS + h];
        float sm0 = s + fdec(g_tmaxb[gg * HEADS + h]);
        float m = fmaxf(sm0, NEG * sm0);
        e12_sh[h * TI + r] = make_float2(__expf(sm0 - m), __expf(NEG * sm0 - m));
        l_sh[h * TI + r] = 0.f;
    }
    __syncthreads();

    constexpr int NSUB = 128 / HT;
    const int pair = tid & (HT - 1);
    const int sub  = NSUB == 1 ? 0 : (tid / HT);
    const int ph   = pair / TI, pr = pair & (TI - 1);
    const float2 E = e12_sh[pair];
    float lacc = 0.f;

    const int colq  = lane & 7;
    const int rgrp  = lane >> 3;
    const int dcol4 = ig * 8 + colq;
    const int myh   = (HEADS == 4) ? ig : 0;
    unsigned long long acc[16];
    #pragma unroll
    for (int k = 0; k < 16; k++) acc[k] = 0ULL;
    const float4* wfg = (const float4*)(g_wf + (gg * L + j0) * C);
    const uint32_t wfb = smem_u32(&wf_sh[0][0][0]);

    auto fill = [&](int jb, int nb) {
        #pragma unroll
        for (int it2 = 0; it2 < 4; it2++) {
            int idx = tid + it2 * 128;
            uint32_t dst = wfb + (uint32_t)(((nb * JC + (idx >> 5)) * 32 + (idx & 31)) * 16);
            cpa16(dst, &wfg[(jb + (idx >> 5)) * 32 + (idx & 31)]);
        }
        CPA_COMMIT();
        uint32_t wd = adj_tr[jb >> 5][pr];
        int bshift = jb & 16;
        #pragma unroll
        for (int jj = sub; jj < JC; jj += NSUB) {
            float2 f = f12_sh[(jb + jj) * HEADS + ph];
            float a = fmaxf(E.x * f.x, E.y * f.y);
            a = ((wd >> (bshift + jj)) & 1u) ? a : 0.f;
            lacc += a;
            alpha_sh[nb][jj * HT + pair] = a;
        }
    };

    fill(0, 0);
    CPA_WAIT0();
    __syncthreads();

    for (int ch = 0; ch < NCH; ch++) {
        int cur = ch & 1;
        if (ch + 1 < NCH) fill((ch + 1) * JC, cur ^ 1);
        #pragma unroll
        for (int jj = 0; jj < JC; jj++) {
            float4 w4 = wf_sh[cur][jj][dcol4];
            unsigned long long wd0 = dup2(w4.x), wd1 = dup2(w4.y);
            unsigned long long wd2 = dup2(w4.z), wd3 = dup2(w4.w);
            const ulonglong2* ap =
                (const ulonglong2*)&alpha_sh[cur][jj * HT + myh * TI + rgrp * 8];
            ulonglong2 q0 = ap[0], q1 = ap[1];
            unsigned long long a2[4] = {q0.x, q0.y, q1.x, q1.y};
            #pragma unroll
            for (int p = 0; p < 4; p++) {
                ffma2(acc[p * 4 + 0], a2[p], wd0);
                ffma2(acc[p * 4 + 1], a2[p], wd1);
                ffma2(acc[p * 4 + 2], a2[p], wd2);
                ffma2(acc[p * 4 + 3], a2[p], wd3);
            }
        }
        CPA_WAIT0();
        __syncthreads();
    }

    if (NSUB == 1) l_sh[pair] = lacc;
    else atomicAdd(&l_sh[pair], lacc);
    __syncthreads();

    if (tid < HT) {
        int r = tid / HEADS, h = tid % HEADS;
        g_pl[((js * BSG + gg) * L + i0 + r) * HEADS + h] = l_sh[h * TI + r];
    }
    float4* po = (float4*)(g_pacc + ((js * BSG + gg) * L) * C);
    #pragma unroll
    for (int p = 0; p < 4; p++) {
        float2 u0 = unpk(acc[p * 4 + 0]);
        float2 u1 = unpk(acc[p * 4 + 1]);
        float2 u2 = unpk(acc[p * 4 + 2]);
        float2 u3 = unpk(acc[p * 4 + 3]);
        int r0loc = rgrp * 8 + 2 * p;
        po[(i0 + r0loc) * 32 + dcol4]     = make_float4(u0.x, u1.x, u2.x, u3.x);
        po[(i0 + r0loc + 1) * 32 + dcol4] = make_float4(u0.y, u1.y, u2.y, u3.y);
    }
}

// ---------------- combine partials + epilogue (layer 2 only) ----------------
template<int HEADS, int MODE>
__global__ void __launch_bounds__(256) k_combine(const float* __restrict__ feats,
                                                 const float* __restrict__ gamma,
                                                 const float* __restrict__ beta,
                                                 float* __restrict__ out) {
    int gid  = blockIdx.x * 256 + threadIdx.x;
    int dcol = gid & 31;
    int row  = gid >> 5;
    constexpr int DH = 32 / HEADS;
    int h = dcol / DH;

    float l = 0.f;
    float4 v = make_float4(0.f, 0.f, 0.f, 0.f);
    #pragma unroll
    for (int ns = 0; ns < NS; ns++) {
        l += g_pl[(ns * BSG * L + row) * HEADS + h];
        float4 p = ((const float4*)(g_pacc + ns * BSG * L * C))[row * 32 + dcol];
        v.x += p.x; v.y += p.y; v.z += p.z; v.w += p.w;
    }
    float rl = 1.f / l;
    v.x *= rl; v.y *= rl; v.z *= rl; v.w *= rl;

    float4 y = ((const float4*)feats)[row * 32 + dcol];
    y.x += v.x; y.y += v.y; y.z += v.z; y.w += v.w;
    float sm = y.x + y.y + y.z + y.w;
    float sq = y.x * y.x + y.y * y.y + y.z * y.z + y.w * y.w;
    #pragma unroll
    for (int off = 16; off > 0; off >>= 1) {
        sm += __shfl_xor_sync(0xffffffffu, sm, off);
        sq += __shfl_xor_sync(0xffffffffu, sq, off);
    }
    float mean = sm * (1.f / 128.f);
    float var  = sq * (1.f / 128.f) - mean * mean;
    float inv  = rsqrtf(var + LNEPS);
    float4 gm = ((const float4*)gamma)[dcol];
    float4 bt = ((const float4*)beta)[dcol];
    float4 o;
    o.x = (y.x - mean) * inv * gm.x + bt.x;
    o.y = (y.y - mean) * inv * gm.y + bt.y;
    o.z = (y.z - mean) * inv * gm.z + bt.z;
    o.w = (y.w - mean) * inv * gm.w + bt.w;
    ((float4*)out)[row * 32 + dcol] = o;
}

// ---------------- launch ----------------
extern "C" void kernel_launch(void* const* d_in, const int* in_sizes, int n_in,
                              void* d_out, int out_size) {
    const float* seg_feats = (const float*)d_in[0];
    const int*   seg_img   = (const int*)d_in[1];
    const float* W1    = (const float*)d_in[3];
    const float* asrc1 = (const float*)d_in[4];
    const float* adst1 = (const float*)d_in[5];
    const float* W2    = (const float*)d_in[6];
    const float* asrc2 = (const float*)d_in[7];
    const float* adst2 = (const float*)d_in[8];
    const float* gamma = (const float*)d_in[9];
    const float* beta  = (const float*)d_in[10];
    float* out = (float*)d_out;

    k_adj_init <<<(BSG * L * 32 + 255) / 256, 256>>>();
    k_adj_build<<<(BSG * HIMG * WIMG + 255) / 256, 256>>>(seg_img);

    // layer 1 (gemm epilogue also feeds g_tmaxb via atomicMax)
    k_gemm_nt<4><<<BSG * 64, 256>>>(seg_feats, W1, asrc1, adst1);
    k_attn_part<4><<<BSG * 32 * NS, 128>>>();

    // layer 2 — gemm<1> fuses the layer-1 combine + ELU into its input path
    // (in == nullptr). g_tmaxb holds layer-1 maxima when layer-2 atomics land:
    // still a valid, deterministic upper bound for the softmax shift.
    k_gemm_nt<1><<<BSG * 64, 256>>>(nullptr, W2, asrc2, adst2);
    k_attn_part<1><<<BSG * 32 * NS, 128>>>();
    k_combine<1, 1><<<BSG * L * 32 / 256, 256>>>(seg_feats, gamma, beta, out);
}

// round 17
// speedup vs baseline: 1.1041x; 1.0695x over previous
#include <cuda_runtime.h>
#include <math.h>
#include <stdint.h>

#define BSG   8          // B*S graphs
#define L     1024       // nodes per graph
#define C     128        // feature dim
#define HIMG  256
#define WIMG  256
#define NEG   0.2f
#define LNEPS 1e-5f
#define NS    8          // j-splits
#define JSPAN (L / NS)   // 128

// ---------------- scratch (static device globals; no allocs) ----------------
__device__ uint32_t g_adj[BSG][L][L / 32];        // 1 MB adjacency bitmask
__device__ float    g_wf[BSG * L * C];            // Wf for current layer
__device__ float    g_h1[BSG * L * C];            // layer-1 output
__device__ float    g_esrc[BSG * L * 4];
__device__ float    g_edst[BSG * L * 4];
__device__ float    g_pacc[NS * BSG * L * C];     // 32 MB partial accumulators
__device__ float    g_pl[NS * BSG * L * 4];       // partial softmax sums [row][head]
__device__ uint32_t g_tmaxb[BSG * 4];             // encoded per-(graph,head) max e_dst

// ---------------- order-preserving float<->uint for atomicMax ----------------
__device__ __forceinline__ uint32_t fenc(float f) {
    uint32_t u = __float_as_uint(f);
    return (u & 0x80000000u) ? ~u : (u | 0x80000000u);
}
__device__ __forceinline__ float fdec(uint32_t k) {
    uint32_t u = (k & 0x80000000u) ? (k ^ 0x80000000u) : ~k;
    return __uint_as_float(u);
}

// ---------------- packed f32x2 helpers (FFMA2) ----------------
__device__ __forceinline__ unsigned long long dup2(float a) {
    unsigned long long r;
    asm("mov.b64 %0, {%1, %1};" : "=l"(r) : "f"(a));
    return r;
}
__device__ __forceinline__ void ffma2(unsigned long long& d,
                                      unsigned long long a, unsigned long long b) {
    asm("fma.rn.f32x2 %0, %1, %2, %0;" : "+l"(d) : "l"(a), "l"(b));
}
__device__ __forceinline__ float2 unpk(unsigned long long v) {
    float lo, hi;
    asm("mov.b64 {%0, %1}, %2;" : "=f"(lo), "=f"(hi) : "l"(v));
    return make_float2(lo, hi);
}

// ---------------- cp.async helpers ----------------
__device__ __forceinline__ uint32_t smem_u32(const void* p) {
    uint32_t a;
    asm("{ .reg .u64 t; cvta.to.shared.u64 t, %1; cvt.u32.u64 %0, t; }" : "=r"(a) : "l"(p));
    return a;
}
__device__ __forceinline__ void cpa16(uint32_t dst, const void* src) {
    asm volatile("cp.async.ca.shared.global [%0], [%1], 16;" :: "r"(dst), "l"(src) : "memory");
}
#define CPA_COMMIT() asm volatile("cp.async.commit_group;" ::: "memory")
#define CPA_WAIT0()  asm volatile("cp.async.wait_group 0;" ::: "memory")

// ---------------- adjacency ----------------
__global__ void k_adj_init() {
    int idx = blockIdx.x * blockDim.x + threadIdx.x;
    if (blockIdx.x == 0 && threadIdx.x < BSG * 4) g_tmaxb[threadIdx.x] = 0u;
    if (idx >= BSG * L * 32) return;
    int w = idx & 31;
    int i = (idx >> 5) & (L - 1);
    ((uint32_t*)g_adj)[idx] = (w == (i >> 5)) ? (1u << (i & 31)) : 0u;
}

__global__ void k_adj_build(const int* __restrict__ img) {
    int idx = blockIdx.x * blockDim.x + threadIdx.x;
    if (idx >= BSG * HIMG * WIMG) return;
    int x  = idx & (WIMG - 1);
    int y  = (idx >> 8) & (HIMG - 1);
    int gg = idx >> 16;
    const int* base = img + gg * HIMG * WIMG;
    int p = base[y * WIMG + x];

    auto edge = [&](int a, int b) {
        if (a > 0 && b > 0 && a != b) {
            int ai = a - 1, bi = b - 1;
            atomicOr(&g_adj[gg][ai][bi >> 5], 1u << (bi & 31));
            atomicOr(&g_adj[gg][bi][ai >> 5], 1u << (ai & 31));
        }
    };
    if (x + 1 < WIMG) edge(p, base[y * WIMG + x + 1]);
    if (y + 1 < HIMG) {
        edge(p, base[(y + 1) * WIMG + x]);
        if (x + 1 < WIMG) edge(p, base[(y + 1) * WIMG + x + 1]);
        if (x > 0)        edge(p, base[(y + 1) * WIMG + x - 1]);
    }
}

// ---------------- NT GEMM (16-row tiles) + fused e_src/e_dst + tmax ----------------
template<int HEADS>
__global__ void __launch_bounds__(256) k_gemm_nt(const float* __restrict__ in,
                                                 const float* __restrict__ W,
                                                 const float* __restrict__ asrc,
                                                 const float* __restrict__ adst) {
    __shared__ float4 xs[16][9];
    __shared__ float4 ws[128][9];
    int tid = threadIdx.x;
    int gg  = blockIdx.x >> 6;
    int r0  = (blockIdx.x & 63) * 16;
    const float* src = in ? (in + gg * L * C) : (g_h1 + gg * L * C);
    const float4* in4 = (const float4*)src;
    const float4* W4  = (const float4*)W;
    int tx = tid & 31, ty = tid >> 5;
    float acc[2][4] = {};

    for (int k0 = 0; k0 < 32; k0 += 8) {
        if (tid < 128) {
            int r = tid >> 3, kq = tid & 7;
            xs[r][kq] = in4[(r0 + r) * 32 + k0 + kq];
        }
        #pragma unroll
        for (int it = 0; it < 4; it++) {
            int idx = tid + it * 256;
            int o = idx >> 3, kq = idx & 7;
            ws[o][kq] = W4[o * 32 + k0 + kq];
        }
        __syncthreads();
        #pragma unroll
        for (int kq = 0; kq < 8; kq++) {
            float4 xv[2], wv[4];
            #pragma unroll
            for (int rr = 0; rr < 2; rr++) xv[rr] = xs[ty * 2 + rr][kq];
            #pragma unroll
            for (int cc = 0; cc < 4; cc++) wv[cc] = ws[tx + 32 * cc][kq];
            #pragma unroll
            for (int rr = 0; rr < 2; rr++)
                #pragma unroll
                for (int cc = 0; cc < 4; cc++)
                    acc[rr][cc] += xv[rr].x * wv[cc].x + xv[rr].y * wv[cc].y
                                 + xv[rr].z * wv[cc].z + xv[rr].w * wv[cc].w;
        }
        __syncthreads();
    }
    float* ob = g_wf + gg * L * C;
    #pragma unroll
    for (int rr = 0; rr < 2; rr++)
        #pragma unroll
        for (int cc = 0; cc < 4; cc++)
            ob[(r0 + ty * 2 + rr) * C + tx + 32 * cc] = acc[rr][cc];

    float as[4], ad[4];
    #pragma unroll
    for (int cc = 0; cc < 4; cc++) {
        int col = tx + 32 * cc;
        as[cc] = asrc[col];
        ad[cc] = adst[col];
    }
    #pragma unroll
    for (int rr = 0; rr < 2; rr++) {
        int row = r0 + ty * 2 + rr;
        if (HEADS == 4) {
            #pragma unroll
            for (int cc = 0; cc < 4; cc++) {
                float ps = acc[rr][cc] * as[cc];
                float pd = acc[rr][cc] * ad[cc];
                #pragma unroll
                for (int off = 16; off > 0; off >>= 1) {
                    ps += __shfl_xor_sync(0xffffffffu, ps, off);
                    pd += __shfl_xor_sync(0xffffffffu, pd, off);
                }
                if (tx == 0) {
                    g_esrc[(gg * L + row) * 4 + cc] = ps;
                    g_edst[(gg * L + row) * 4 + cc] = pd;
                    atomicMax(&g_tmaxb[gg * 4 + cc], fenc(pd));
                }
            }
        } else {
            float ps = 0.f, pd = 0.f;
            #pragma unroll
            for (int cc = 0; cc < 4; cc++) {
                ps += acc[rr][cc] * as[cc];
                pd += acc[rr][cc] * ad[cc];
            }
            #pragma unroll
            for (int off = 16; off > 0; off >>= 1) {
                ps += __shfl_xor_sync(0xffffffffu, ps, off);
                pd += __shfl_xor_sync(0xffffffffu, pd, off);
            }
            if (tx == 0) {
                g_esrc[(gg * L + row)] = ps;
                g_edst[(gg * L + row)] = pd;
                atomicMax(&g_tmaxb[gg], fenc(pd));
            }
        }
    }
}

// ---------------- partial masked attention over one j-split ----------------
// Round-14 configuration (best verified): 128 threads / 4 warps, 8 rows/thread,
// column-group tiling, row-paired f32x2 acc, double buffer + cp.async,
// alpha = mask * max(E1_i*F1_j, E2_i*F2_j). NS=8 (JSPAN=128) for wave balance.
template<int HEADS>
__global__ void __launch_bounds__(128) k_attn_part() {
    constexpr int TI = 32, JC = 16, HT = HEADS * TI, NCH = JSPAN / JC;
    __shared__ __align__(16) float2 f12_sh[JSPAN * HEADS];
    __shared__ __align__(16) float4 wf_sh[2][JC][32];
    __shared__ __align__(16) float alpha_sh[2][JC * HT];
    __shared__ uint32_t adj_tr[JSPAN / 32][TI];
    __shared__ float2 e12_sh[HT];
    __shared__ float l_sh[HT];

    int tid  = threadIdx.x;
    int lane = tid & 31, ig = tid >> 5;
    int b    = blockIdx.x;                       // BSG*32*NS blocks
    int js   = b & (NS - 1);
    int it   = (b >> 3) & 31;
    int gg   = b >> 8;
    int i0   = it * TI;
    int j0   = js * JSPAN;

    {
        const float* tg = g_edst + (gg * L + j0) * HEADS;
        for (int idx = tid; idx < JSPAN * HEADS; idx += 128) {
            int h = idx & (HEADS - 1);
            float tmax = fdec(g_tmaxb[gg * HEADS + h]);
            float d = tg[idx] - tmax;
            f12_sh[idx] = make_float2(__expf(d), __expf(NEG * d));
        }
    }
    for (int idx = tid; idx < (JSPAN / 32) * TI; idx += 128) {
        int w = idx / TI, r = idx % TI;
        adj_tr[w][r] = g_adj[gg][i0 + r][(j0 >> 5) + w];
    }
    if (tid < HT) {
        int r = tid / HEADS, h = tid & (HEADS - 1);
        float s = g_esrc[(gg * L + i0 + r) * HEADS + h];
        float sm0 = s + fdec(g_tmaxb[gg * HEADS + h]);
        float m = fmaxf(sm0, NEG * sm0);
        e12_sh[h * TI + r] = make_float2(__expf(sm0 - m), __expf(NEG * sm0 - m));
        l_sh[h * TI + r] = 0.f;
    }
    __syncthreads();

    constexpr int NSUB = 128 / HT;
    const int pair = tid & (HT - 1);
    const int sub  = NSUB == 1 ? 0 : (tid / HT);
    const int ph   = pair / TI, pr = pair & (TI - 1);
    const float2 E = e12_sh[pair];
    float lacc = 0.f;

    const int colq  = lane & 7;
    const int rgrp  = lane >> 3;
    const int dcol4 = ig * 8 + colq;
    const int myh   = (HEADS == 4) ? ig : 0;
    unsigned long long acc[16];
    #pragma unroll
    for (int k = 0; k < 16; k++) acc[k] = 0ULL;
    const float4* wfg = (const float4*)(g_wf + (gg * L + j0) * C);
    const uint32_t wfb = smem_u32(&wf_sh[0][0][0]);

    auto fill = [&](int jb, int nb) {
        #pragma unroll
        for (int it2 = 0; it2 < 4; it2++) {
            int idx = tid + it2 * 128;
            uint32_t dst = wfb + (uint32_t)(((nb * JC + (idx >> 5)) * 32 + (idx & 31)) * 16);
            cpa16(dst, &wfg[(jb + (idx >> 5)) * 32 + (idx & 31)]);
        }
        CPA_COMMIT();
        uint32_t wd = adj_tr[jb >> 5][pr];
        int bshift = jb & 16;
        #pragma unroll
        for (int jj = sub; jj < JC; jj += NSUB) {
            float2 f = f12_sh[(jb + jj) * HEADS + ph];
            float a = fmaxf(E.x * f.x, E.y * f.y);
            a = ((wd >> (bshift + jj)) & 1u) ? a : 0.f;
            lacc += a;
            alpha_sh[nb][jj * HT + pair] = a;
        }
    };

    fill(0, 0);
    CPA_WAIT0();
    __syncthreads();

    for (int ch = 0; ch < NCH; ch++) {           // 8 chunks
        int cur = ch & 1;
        if (ch + 1 < NCH) fill((ch + 1) * JC, cur ^ 1);
        #pragma unroll
        for (int jj = 0; jj < JC; jj++) {
            float4 w4 = wf_sh[cur][jj][dcol4];
            unsigned long long wd0 = dup2(w4.x), wd1 = dup2(w4.y);
            unsigned long long wd2 = dup2(w4.z), wd3 = dup2(w4.w);
            const ulonglong2* ap =
                (const ulonglong2*)&alpha_sh[cur][jj * HT + myh * TI + rgrp * 8];
            ulonglong2 q0 = ap[0], q1 = ap[1];
            unsigned long long a2[4] = {q0.x, q0.y, q1.x, q1.y};
            #pragma unroll
            for (int p = 0; p < 4; p++) {
                ffma2(acc[p * 4 + 0], a2[p], wd0);
                ffma2(acc[p * 4 + 1], a2[p], wd1);
                ffma2(acc[p * 4 + 2], a2[p], wd2);
                ffma2(acc[p * 4 + 3], a2[p], wd3);
            }
        }
        CPA_WAIT0();
        __syncthreads();
    }

    if (NSUB == 1) l_sh[pair] = lacc;
    else atomicAdd(&l_sh[pair], lacc);
    __syncthreads();

    // write partials — l_sh is [head][row]; g_pl is [row][head]: transpose.
    if (tid < HT) {
        int r = tid / HEADS, h = tid % HEADS;
        g_pl[((js * BSG + gg) * L + i0 + r) * HEADS + h] = l_sh[h * TI + r];
    }
    float4* po = (float4*)(g_pacc + ((js * BSG + gg) * L) * C);
    #pragma unroll
    for (int p = 0; p < 4; p++) {
        float2 u0 = unpk(acc[p * 4 + 0]);
        float2 u1 = unpk(acc[p * 4 + 1]);
        float2 u2 = unpk(acc[p * 4 + 2]);
        float2 u3 = unpk(acc[p * 4 + 3]);
        int r0loc = rgrp * 8 + 2 * p;
        po[(i0 + r0loc) * 32 + dcol4]     = make_float4(u0.x, u1.x, u2.x, u3.x);
        po[(i0 + r0loc + 1) * 32 + dcol4] = make_float4(u0.y, u1.y, u2.y, u3.y);
    }
}

// ---------------- combine partials + epilogue ----------------
template<int HEADS, int MODE>
__global__ void __launch_bounds__(256) k_combine(const float* __restrict__ feats,
                                                 const float* __restrict__ gamma,
                                                 const float* __restrict__ beta,
                                                 float* __restrict__ out) {
    int gid  = blockIdx.x * 256 + threadIdx.x;   // BSG*L*32 threads
    int dcol = gid & 31;
    int row  = gid >> 5;
    constexpr int DH = 32 / HEADS;
    int h = dcol / DH;

    float l = 0.f;
    float4 v = make_float4(0.f, 0.f, 0.f, 0.f);
    #pragma unroll
    for (int ns = 0; ns < NS; ns++) {
        l += g_pl[(ns * BSG * L + row) * HEADS + h];
        float4 p = ((const float4*)(g_pacc + ns * BSG * L * C))[row * 32 + dcol];
        v.x += p.x; v.y += p.y; v.z += p.z; v.w += p.w;
    }
    float rl = 1.f / l;
    v.x *= rl; v.y *= rl; v.z *= rl; v.w *= rl;

    if (MODE == 0) {
        v.x = v.x > 0.f ? v.x : expm1f(v.x);
        v.y = v.y > 0.f ? v.y : expm1f(v.y);
        v.z = v.z > 0.f ? v.z : expm1f(v.z);
        v.w = v.w > 0.f ? v.w : expm1f(v.w);
        ((float4*)g_h1)[row * 32 + dcol] = v;
    } else {
        float4 y = ((const float4*)feats)[row * 32 + dcol];
        y.x += v.x; y.y += v.y; y.z += v.z; y.w += v.w;
        float sm = y.x + y.y + y.z + y.w;
        float sq = y.x * y.x + y.y * y.y + y.z * y.z + y.w * y.w;
        #pragma unroll
        for (int off = 16; off > 0; off >>= 1) {
            sm += __shfl_xor_sync(0xffffffffu, sm, off);
            sq += __shfl_xor_sync(0xffffffffu, sq, off);
        }
        float mean = sm * (1.f / 128.f);
        float var  = sq * (1.f / 128.f) - mean * mean;
        float inv  = rsqrtf(var + LNEPS);
        float4 gm = ((const float4*)gamma)[dcol];
        float4 bt = ((const float4*)beta)[dcol];
        float4 o;
        o.x = (y.x - mean) * inv * gm.x + bt.x;
        o.y = (y.y - mean) * inv * gm.y + bt.y;
        o.z = (y.z - mean) * inv * gm.z + bt.z;
        o.w = (y.w - mean) * inv * gm.w + bt.w;
        ((float4*)out)[row * 32 + dcol] = o;
    }
}

// ---------------- launch ----------------
extern "C" void kernel_launch(void* const* d_in, const int* in_sizes, int n_in,
                              void* d_out, int out_size) {
    const float* seg_feats = (const float*)d_in[0];
    const int*   seg_img   = (const int*)d_in[1];
    const float* W1    = (const float*)d_in[3];
    const float* asrc1 = (const float*)d_in[4];
    const float* adst1 = (const float*)d_in[5];
    const float* W2    = (const float*)d_in[6];
    const float* asrc2 = (const float*)d_in[7];
    const float* adst2 = (const float*)d_in[8];
    const float* gamma = (const float*)d_in[9];
    const float* beta  = (const float*)d_in[10];
    float* out = (float*)d_out;

    k_adj_init <<<(BSG * L * 32 + 255) / 256, 256>>>();
    k_adj_build<<<(BSG * HIMG * WIMG + 255) / 256, 256>>>(seg_img);

    // layer 1 (gemm epilogue also feeds g_tmaxb via atomicMax)
    k_gemm_nt<4><<<BSG * 64, 256>>>(seg_feats, W1, asrc1, adst1);
    k_attn_part<4><<<BSG * 32 * NS, 128>>>();
    k_combine<4, 0><<<BSG * L * 32 / 256, 256>>>(nullptr, nullptr, nullptr, nullptr);

    // layer 2 — g_tmaxb zeroed by k_adj_init each launch; layer-2 atomics land on
    // layer-1 maxima, still a valid (deterministic) upper bound for the shift.
    k_gemm_nt<1><<<BSG * 64, 256>>>(nullptr, W2, asrc2, adst2);
    k_attn_part<1><<<BSG * 32 * NS, 128>>>();
    k_combine<1, 1><<<BSG * L * 32 / 256, 256>>>(seg_feats, gamma, beta, out);
}